// round 1
// baseline (speedup 1.0000x reference)
#include <cuda_runtime.h>
#include <math.h>

#define BB 32
#define SS 2048
#define HH 768
#define EE 2
#define MTOT (BB*SS)
#define LN_EPS 1e-5f

// Scratch (no allocations allowed)
__device__ float g_pooled[BB*HH];
__device__ float g_probs[BB*EE];
__device__ int   g_idx[BB];

// ---------------------------------------------------------------------------
// Kernel 1: mean over sequence dim. inputs [B, S, H] -> g_pooled [B, H]
// ---------------------------------------------------------------------------
__global__ void pool_kernel(const float* __restrict__ in) {
    int idx = blockIdx.x * blockDim.x + threadIdx.x;
    if (idx >= BB * HH) return;
    int b = idx / HH;
    int h = idx - b * HH;
    const float* p = in + (size_t)b * SS * HH + h;
    float s0 = 0.f, s1 = 0.f, s2 = 0.f, s3 = 0.f;
    #pragma unroll 4
    for (int i = 0; i < SS; i += 4) {
        s0 += p[(size_t)(i + 0) * HH];
        s1 += p[(size_t)(i + 1) * HH];
        s2 += p[(size_t)(i + 2) * HH];
        s3 += p[(size_t)(i + 3) * HH];
    }
    g_pooled[idx] = (s0 + s1 + s2 + s3) * (1.0f / SS);
}

// ---------------------------------------------------------------------------
// Kernel 2: LayerNorm -> router linear -> softmax -> argmax, per batch row.
// One block (256 threads) per batch.
// ---------------------------------------------------------------------------
__global__ void router_kernel(const float* __restrict__ gamma,
                              const float* __restrict__ beta,
                              const float* __restrict__ rw,
                              const float* __restrict__ rb) {
    int b = blockIdx.x;
    int t = threadIdx.x;  // 256 threads, 3 h-values each (768 = 3*256)
    __shared__ float red[256];

    float x0 = g_pooled[b * HH + t];
    float x1 = g_pooled[b * HH + t + 256];
    float x2 = g_pooled[b * HH + t + 512];

    // mean
    red[t] = x0 + x1 + x2;
    __syncthreads();
    for (int o = 128; o > 0; o >>= 1) { if (t < o) red[t] += red[t + o]; __syncthreads(); }
    float mu = red[0] * (1.0f / HH);
    __syncthreads();

    // variance (population)
    float d0 = x0 - mu, d1 = x1 - mu, d2 = x2 - mu;
    red[t] = d0 * d0 + d1 * d1 + d2 * d2;
    __syncthreads();
    for (int o = 128; o > 0; o >>= 1) { if (t < o) red[t] += red[t + o]; __syncthreads(); }
    float rstd = rsqrtf(red[0] * (1.0f / HH) + LN_EPS);
    __syncthreads();

    // normalize + router matvec (E=2)
    float n0 = d0 * rstd * gamma[t]       + beta[t];
    float n1 = d1 * rstd * gamma[t + 256] + beta[t + 256];
    float n2 = d2 * rstd * gamma[t + 512] + beta[t + 512];
    float l0 = n0 * rw[t * EE]           + n1 * rw[(t + 256) * EE]     + n2 * rw[(t + 512) * EE];
    float l1 = n0 * rw[t * EE + 1]       + n1 * rw[(t + 256) * EE + 1] + n2 * rw[(t + 512) * EE + 1];

    red[t] = l0;
    __syncthreads();
    for (int o = 128; o > 0; o >>= 1) { if (t < o) red[t] += red[t + o]; __syncthreads(); }
    l0 = red[0];
    __syncthreads();
    red[t] = l1;
    __syncthreads();
    for (int o = 128; o > 0; o >>= 1) { if (t < o) red[t] += red[t + o]; __syncthreads(); }

    if (t == 0) {
        l1 = red[0];
        l0 += rb[0];
        l1 += rb[1];
        float m  = fmaxf(l0, l1);
        float e0 = expf(l0 - m);
        float e1 = expf(l1 - m);
        float inv = 1.0f / (e0 + e1);
        g_probs[b * 2 + 0] = e0 * inv;
        g_probs[b * 2 + 1] = e1 * inv;
        g_idx[b] = (l1 > l0) ? 1 : 0;  // argmax, ties -> 0 (matches jnp.argmax)
    }
}

// ---------------------------------------------------------------------------
// Kernel 3: aux (load-balance) loss -> out[B*S*H]
// ---------------------------------------------------------------------------
__global__ void aux_kernel(float* __restrict__ out) {
    float a0 = 0.f, a1 = 0.f;
    for (int b = 0; b < BB; b++) { a0 += g_probs[2 * b]; a1 += g_probs[2 * b + 1]; }
    a0 *= (1.0f / BB);
    a1 *= (1.0f / BB);
    float d0 = a0 - 0.5f, d1 = a1 - 0.5f;
    out[0] = 0.01f * 0.5f * (d0 * d0 + d1 * d1);
}

// ---------------------------------------------------------------------------
// GELU (tanh approximation, matches jax.nn.gelu approximate=True)
// ---------------------------------------------------------------------------
__device__ __forceinline__ float gelu_f(float x) {
    float u = 0.7978845608028654f * x * (1.0f + 0.044715f * x * x);
    float a = __expf(2.0f * fabsf(u));            // saturates safely to +inf
    float t = copysignf(1.0f - 2.0f / (a + 1.0f), u);
    return 0.5f * x * (1.0f + t);
}

// ---------------------------------------------------------------------------
// Kernel 4: expert GEMM + bias + GELU.
// C[m, n] = gelu( sum_k A[m,k] * W_e[k,n] + bias_e[n] ),  e = g_idx[m / S]
// 128x128x16 tiles, 256 threads, 8x8 per-thread microtile, fp32.
// ---------------------------------------------------------------------------
__global__ __launch_bounds__(256, 2) void gemm_gelu_kernel(
    const float* __restrict__ A,     // [MTOT, H]
    const float* __restrict__ W,     // [E, H, H]
    const float* __restrict__ bias,  // [E, H]
    float* __restrict__ C)           // [MTOT, H]
{
    const int BM = 128, BN = 128, BK = 16;
    __shared__ float As[BK][BM + 4];   // transposed A tile (132-float stride keeps 16B align)
    __shared__ float Bs[BK][BN + 4];

    int tid = threadIdx.x;
    int tx = tid & 15;          // N direction (0..15)
    int ty = tid >> 4;          // M direction (0..15)
    int m0 = blockIdx.y * BM;
    int n0 = blockIdx.x * BN;

    int bat = m0 >> 11;         // 2048 rows per batch; 128 | 2048 so tile is single-expert
    int e = g_idx[bat];
    const float* Wp = W + (size_t)e * HH * HH;
    const float* bp = bias + e * HH;
    const float* Ap = A + (size_t)m0 * HH;

    // global-load assignments
    int aRow  = tid >> 2;       // 0..63  (two rows: aRow, aRow+64)
    int aCol4 = tid & 3;        // 0..3   (float4 within 16-float K slab)
    int bRow  = tid >> 5;       // 0..7   (two rows: bRow, bRow+8)
    int bCol4 = tid & 31;       // 0..31  (float4 within 128-float N tile)

    float acc[8][8];
    #pragma unroll
    for (int i = 0; i < 8; i++)
        #pragma unroll
        for (int j = 0; j < 8; j++) acc[i][j] = 0.f;

    for (int kt = 0; kt < HH; kt += BK) {
        float4 a0 = *(const float4*)(Ap + (size_t)aRow        * HH + kt + aCol4 * 4);
        float4 a1 = *(const float4*)(Ap + (size_t)(aRow + 64) * HH + kt + aCol4 * 4);
        float4 b0 = *(const float4*)(Wp + (size_t)(kt + bRow)     * HH + n0 + bCol4 * 4);
        float4 b1 = *(const float4*)(Wp + (size_t)(kt + bRow + 8) * HH + n0 + bCol4 * 4);

        __syncthreads();  // previous iteration's consumers done

        As[aCol4 * 4 + 0][aRow] = a0.x;
        As[aCol4 * 4 + 1][aRow] = a0.y;
        As[aCol4 * 4 + 2][aRow] = a0.z;
        As[aCol4 * 4 + 3][aRow] = a0.w;
        As[aCol4 * 4 + 0][aRow + 64] = a1.x;
        As[aCol4 * 4 + 1][aRow + 64] = a1.y;
        As[aCol4 * 4 + 2][aRow + 64] = a1.z;
        As[aCol4 * 4 + 3][aRow + 64] = a1.w;
        *(float4*)&Bs[bRow][bCol4 * 4]     = b0;
        *(float4*)&Bs[bRow + 8][bCol4 * 4] = b1;

        __syncthreads();

        #pragma unroll
        for (int k = 0; k < BK; k++) {
            float ar[8], br[8];
            *(float4*)(ar)     = *(const float4*)&As[k][ty * 8];
            *(float4*)(ar + 4) = *(const float4*)&As[k][ty * 8 + 4];
            *(float4*)(br)     = *(const float4*)&Bs[k][tx * 8];
            *(float4*)(br + 4) = *(const float4*)&Bs[k][tx * 8 + 4];
            #pragma unroll
            for (int i = 0; i < 8; i++)
                #pragma unroll
                for (int j = 0; j < 8; j++)
                    acc[i][j] = fmaf(ar[i], br[j], acc[i][j]);
        }
    }

    // epilogue: bias + gelu + store
    float bv[8];
    #pragma unroll
    for (int j = 0; j < 8; j++) bv[j] = bp[n0 + tx * 8 + j];

    #pragma unroll
    for (int i = 0; i < 8; i++) {
        int m = m0 + ty * 8 + i;
        float o[8];
        #pragma unroll
        for (int j = 0; j < 8; j++) o[j] = gelu_f(acc[i][j] + bv[j]);
        *(float4*)&C[(size_t)m * HH + n0 + tx * 8]     = *(float4*)(o);
        *(float4*)&C[(size_t)m * HH + n0 + tx * 8 + 4] = *(float4*)(o + 4);
    }
}

// ---------------------------------------------------------------------------
// Launch
// ---------------------------------------------------------------------------
extern "C" void kernel_launch(void* const* d_in, const int* in_sizes, int n_in,
                              void* d_out, int out_size) {
    const float* inputs   = (const float*)d_in[0];  // [B, S, H]
    const float* ln_gamma = (const float*)d_in[1];  // [H]
    const float* ln_beta  = (const float*)d_in[2];  // [H]
    const float* router_w = (const float*)d_in[3];  // [H, E]
    const float* router_b = (const float*)d_in[4];  // [E]
    const float* expert_w = (const float*)d_in[5];  // [E, H, H]
    const float* expert_b = (const float*)d_in[6];  // [E, H]
    float* out = (float*)d_out;

    pool_kernel<<<(BB * HH + 255) / 256, 256>>>(inputs);
    router_kernel<<<BB, 256>>>(ln_gamma, ln_beta, router_w, router_b);

    dim3 grid(HH / 128, MTOT / 128);  // (6, 512)
    gemm_gelu_kernel<<<grid, 256>>>(inputs, expert_w, expert_b, out);

    if (out_size > BB * SS * HH) {
        aux_kernel<<<1, 1>>>(out + (size_t)BB * SS * HH);
    }
}